// round 13
// baseline (speedup 1.0000x reference)
#include <cuda_runtime.h>
#include <cuda_fp16.h>
#include <cstdint>
#include <math.h>

#define D_MODEL 1024
#define NHEAD   16
#define HDIM    64
#define BATCH   2
#define SEQ     2048
#define MTOK    (BATCH * SEQ)   // 4096

// -------- scratch (static device globals; no allocation allowed) --------
__device__ __half g_xq[MTOK * D_MODEL];       // fp16 query input
__device__ __half g_xk[MTOK * D_MODEL];       // fp16 key input
__device__ __half g_xv[MTOK * D_MODEL];       // fp16 value input
__device__ __half g_wq[D_MODEL * D_MODEL];    // fp16 Wq * 0.125 * log2(e)
__device__ __half g_wk[D_MODEL * D_MODEL];    // fp16 Wk
__device__ __half g_wv[D_MODEL * D_MODEL];    // fp16 Wv
__device__ __half g_wo[D_MODEL * D_MODEL];    // fp16 Wo
__device__ __half g_qh[MTOK * D_MODEL];       // fp16 Q (pre-scaled, log2 domain)
__device__ __half g_kh[MTOK * D_MODEL];       // fp16 K
__device__ __half g_vh[MTOK * D_MODEL];       // fp16 V
__device__ __half g_ch[MTOK * D_MODEL];       // fp16 ctx

// ======================= helpers =======================
__device__ __forceinline__ uint32_t smem_u32(const void* p) {
    uint32_t a;
    asm("{ .reg .u64 t; cvta.to.shared.u64 t, %1; cvt.u32.u64 %0, t; }"
        : "=r"(a) : "l"(p));
    return a;
}

__device__ __forceinline__ float ex2(float x) {
    float y;
    asm("ex2.approx.ftz.f32 %0, %1;" : "=f"(y) : "f"(x));
    return y;
}

__device__ __forceinline__ void mma16h(float* d, const unsigned* a,
                                       unsigned b0, unsigned b1) {
    asm volatile(
        "mma.sync.aligned.m16n8k16.row.col.f32.f16.f16.f32 "
        "{%0,%1,%2,%3}, {%4,%5,%6,%7}, {%8,%9}, {%0,%1,%2,%3};"
        : "+f"(d[0]), "+f"(d[1]), "+f"(d[2]), "+f"(d[3])
        : "r"(a[0]), "r"(a[1]), "r"(a[2]), "r"(a[3]), "r"(b0), "r"(b1));
}

__device__ __forceinline__ void ldsm4(unsigned* r, uint32_t a) {
    asm volatile("ldmatrix.sync.aligned.m8n8.x4.shared.b16 {%0,%1,%2,%3}, [%4];"
                 : "=r"(r[0]), "=r"(r[1]), "=r"(r[2]), "=r"(r[3]) : "r"(a));
}
__device__ __forceinline__ void ldsm4t(unsigned* r, uint32_t a) {
    asm volatile("ldmatrix.sync.aligned.m8n8.x4.trans.shared.b16 {%0,%1,%2,%3}, [%4];"
                 : "=r"(r[0]), "=r"(r[1]), "=r"(r[2]), "=r"(r[3]) : "r"(a));
}

#define CP_A16(dst, src) \
    asm volatile("cp.async.ca.shared.global [%0], [%1], 16;" :: "r"(dst), "l"(src) : "memory")
#define CP_A4(dst, src) \
    asm volatile("cp.async.ca.shared.global [%0], [%1], 4;" :: "r"(dst), "l"(src) : "memory")
#define CP_COMMIT() asm volatile("cp.async.commit_group;" ::: "memory")
#define CP_WAIT(n)  asm volatile("cp.async.wait_group %0;" :: "n"(n) : "memory")

// ======================= pre-convert: fp32 -> fp16 =======================
#define QSCALE 0.18033688f   // 0.125 * log2(e)

__global__ __launch_bounds__(256)
void cvt_all(const float* __restrict__ q, const float* __restrict__ k,
             const float* __restrict__ v, const float* __restrict__ wq,
             const float* __restrict__ wk, const float* __restrict__ wv,
             const float* __restrict__ wo,
             __half* __restrict__ xq, __half* __restrict__ xk,
             __half* __restrict__ xv, __half* __restrict__ hwq,
             __half* __restrict__ hwk, __half* __restrict__ hwv,
             __half* __restrict__ hwo)
{
    const float* src; __half* dst; int n; float sc = 1.0f;
    switch (blockIdx.y) {
        case 0: src = q;  dst = xq;  n = MTOK * D_MODEL; break;
        case 1: src = k;  dst = xk;  n = MTOK * D_MODEL; break;
        case 2: src = v;  dst = xv;  n = MTOK * D_MODEL; break;
        case 3: src = wq; dst = hwq; n = D_MODEL * D_MODEL; sc = QSCALE; break;
        case 4: src = wk; dst = hwk; n = D_MODEL * D_MODEL; break;
        case 5: src = wv; dst = hwv; n = D_MODEL * D_MODEL; break;
        default: src = wo; dst = hwo; n = D_MODEL * D_MODEL; break;
    }
    int i = (blockIdx.x * 256 + threadIdx.x) * 4;
    if (i < n) {
        float4 f = *(const float4*)(src + i);
        *(__half2*)(dst + i)     = __floats2half2_rn(f.x * sc, f.y * sc);
        *(__half2*)(dst + i + 2) = __floats2half2_rn(f.z * sc, f.w * sc);
    }
}

// ======================= GEMM (pure fp16, cp.async 3-stage, BK=64) =======================
#define G2ST   144                 // row stride bytes (72 halves; conflict-free LDSM)
#define G2_OP  (128 * G2ST)        // 18432 per operand per stage
#define G2_STAGE (2 * G2_OP)       // 36864
#define G2_SMEM  (3 * G2_STAGE)    // 110592

__global__ __launch_bounds__(256, 2)
void gemm_h2(const __half* __restrict__ X, const __half* __restrict__ W,
             const float* __restrict__ bias, void* __restrict__ Yv, int outmode)
{
    extern __shared__ char smem[];
    const uint32_t sb = smem_u32(smem);

    const int tid  = threadIdx.x;
    const int lane = tid & 31;
    const int wid  = tid >> 5;
    const int bm   = blockIdx.y * 128;
    const int bn   = blockIdx.x * 128;
    const int wm   = (wid & 3) * 32;
    const int wn   = (wid >> 2) * 64;
    const int g    = lane >> 2;
    const int t    = lane & 3;
    const int K    = D_MODEL;

    const int l7  = lane & 7;
    const int lb3 = (lane >> 3) & 1;
    const int lb4 = lane >> 4;

    int lrow[4], lc[4];
#pragma unroll
    for (int i = 0; i < 4; i++) {
        int idx = tid + i * 256;
        lrow[i] = idx >> 3;
        lc[i]   = idx & 7;
    }

    auto issue = [&](int s) {
        uint32_t st = sb + (uint32_t)(s % 3) * G2_STAGE;
        int k0 = s * 64;
#pragma unroll
        for (int i = 0; i < 4; i++) {
            uint32_t doff = (uint32_t)(lrow[i] * G2ST + lc[i] * 16);
            CP_A16(st + doff,         X + (size_t)(bm + lrow[i]) * K + k0 + lc[i] * 8);
            CP_A16(st + G2_OP + doff, W + (size_t)(bn + lrow[i]) * K + k0 + lc[i] * 8);
        }
        CP_COMMIT();
    };

    uint32_t aoffb[2];
#pragma unroll
    for (int mt = 0; mt < 2; mt++)
        aoffb[mt] = (uint32_t)((wm + mt * 16 + l7 + (lane & 8)) * G2ST) + lb4 * 16;
    const uint32_t boffb = (uint32_t)((wn + l7 + lb4 * 8) * G2ST) + lb3 * 16;

    float acc[2][8][4];
#pragma unroll
    for (int mt = 0; mt < 2; mt++)
#pragma unroll
        for (int nt = 0; nt < 8; nt++)
#pragma unroll
            for (int e = 0; e < 4; e++) acc[mt][nt][e] = 0.0f;

    const int NS = K / 64;   // 16
    issue(0); issue(1);

    for (int s = 0; s < NS; s++) {
        if (s + 1 < NS) CP_WAIT(1);
        else            CP_WAIT(0);
        __syncthreads();
        if (s + 2 < NS) issue(s + 2);

        uint32_t ab = sb + (uint32_t)(s % 3) * G2_STAGE;
        uint32_t bb = ab + G2_OP;
#pragma unroll
        for (int s16 = 0; s16 < 4; s16++) {
            unsigned a[2][4];
            ldsm4(a[0], ab + aoffb[0] + s16 * 32);
            ldsm4(a[1], ab + aoffb[1] + s16 * 32);
#pragma unroll
            for (int np = 0; np < 4; np++) {
                unsigned b4[4];
                ldsm4(b4, bb + boffb + np * 16 * G2ST + s16 * 32);
                mma16h(acc[0][2 * np],     a[0], b4[0], b4[1]);
                mma16h(acc[0][2 * np + 1], a[0], b4[2], b4[3]);
                mma16h(acc[1][2 * np],     a[1], b4[0], b4[1]);
                mma16h(acc[1][2 * np + 1], a[1], b4[2], b4[3]);
            }
        }
    }

#pragma unroll
    for (int mt = 0; mt < 2; mt++)
#pragma unroll
        for (int hh = 0; hh < 2; hh++) {
            int row = bm + wm + mt * 16 + g + hh * 8;
#pragma unroll
            for (int nt = 0; nt < 8; nt++) {
                int col = bn + wn + nt * 8 + t * 2;
                float x = acc[mt][nt][hh * 2 + 0];
                float y = acc[mt][nt][hh * 2 + 1];
                if (outmode) {
                    *(__half2*)((__half*)Yv + (size_t)row * D_MODEL + col) =
                        __floats2half2_rn(x, y);
                } else {
                    float2 v;
                    v.x = x + bias[col];
                    v.y = y + bias[col + 1];
                    *(float2*)((float*)Yv + (size_t)row * D_MODEL + col) = v;
                }
            }
        }
}

// ======================= Flash attention: fp16 mma + ldmatrix =======================
// exp2 domain; 3-stage K/V ring, ONE block barrier per key-tile (wait->sync->issue).
#define HSTB 144                       // row stride bytes (72 halves)
#define QS_B   0                       // 128 rows
#define KS_B(s) (18432 + (s) * 9216)   // 64 rows, 3 stages
#define VS_B(s) (46080 + (s) * 9216)   // 64 rows, 3 stages
#define PS_B   73728                   // 128 rows
#define MK_B(s) (92160 + (s) * 256)    // 64 ints, 3 stages
#define ATT_SMEM_BYTES (92928)

__global__ __launch_bounds__(256, 2)
void attn_h(const __half* __restrict__ Qb, const __half* __restrict__ Kb,
            const __half* __restrict__ Vb, const int* __restrict__ mask,
            __half* __restrict__ ctx)
{
    extern __shared__ char sm[];
    const uint32_t sb = smem_u32(sm);

    const int tid  = threadIdx.x;
    const int lane = tid & 31;
    const int wid  = tid >> 5;
    const int g    = lane >> 2;
    const int t    = lane & 3;
    const int q0   = blockIdx.x * 128;
    const int hd   = blockIdx.y;
    const int b    = blockIdx.z;

    const __half* Qg = Qb + (size_t)(b * SEQ) * D_MODEL + hd * HDIM;
    const __half* Kg = Kb + (size_t)(b * SEQ) * D_MODEL + hd * HDIM;
    const __half* Vg = Vb + (size_t)(b * SEQ) * D_MODEL + hd * HDIM;
    const int*    Mg = mask + b * SEQ;

    int jr[2], jc[2];
#pragma unroll
    for (int i = 0; i < 2; i++) {
        int idx = tid + i * 256;
        jr[i] = idx >> 3;
        jc[i] = idx & 7;
    }

    auto issue_tile = [&](int st, int kb) {
#pragma unroll
        for (int i = 0; i < 2; i++) {
            uint32_t doff = (uint32_t)(jr[i] * HSTB + jc[i] * 16);
            CP_A16(sb + KS_B(st) + doff, Kg + (size_t)(kb + jr[i]) * D_MODEL + jc[i] * 8);
            CP_A16(sb + VS_B(st) + doff, Vg + (size_t)(kb + jr[i]) * D_MODEL + jc[i] * 8);
        }
        if (tid < 64) CP_A4(sb + MK_B(st) + tid * 4, Mg + kb + tid);
        CP_COMMIT();
    };

    issue_tile(0, 0);
    issue_tile(1, 64);

    // ---- Q tile -> smem (raw fp16, pure copy) ----
#pragma unroll
    for (int i = 0; i < 4; i++) {
        int idx = tid + i * 256;
        int row = idx >> 3;
        int c8  = idx & 7;
        *(uint4*)(sm + QS_B + row * HSTB + c8 * 16) =
            *(const uint4*)(Qg + (size_t)(q0 + row) * D_MODEL + c8 * 8);
    }

    const int l7  = lane & 7;
    const int lb3 = (lane >> 3) & 1;
    const int lb4 = lane >> 4;
    const uint32_t qa = sb + QS_B + (uint32_t)((wid * 16 + l7 + (lane & 8)) * HSTB) + lb4 * 16;
    const uint32_t pa = sb + PS_B + (uint32_t)((wid * 16 + l7 + (lane & 8)) * HSTB) + lb4 * 16;
    const uint32_t koff = (uint32_t)((l7 + lb4 * 8) * HSTB) + lb3 * 16;
    const uint32_t voff = (uint32_t)((l7 + lb3 * 8) * HSTB) + lb4 * 16;

    float oacc[8][4];
#pragma unroll
    for (int dt = 0; dt < 8; dt++)
#pragma unroll
        for (int e = 0; e < 4; e++) oacc[dt][e] = 0.0f;
    float mrun[2] = {-1e30f, -1e30f};
    float lrun[2] = {0.0f, 0.0f};

    const int r = wid * 16 + g;
    const unsigned FULL = 0xffffffffu;
    const int NT = SEQ / 64;   // 32

    for (int ti = 0; ti < NT; ti++) {
        // one barrier per tile: wait -> sync -> issue (overwrites stage consumed at ti-1,
        // which the barrier has just proven complete for ALL warps)
        if (ti + 1 < NT) CP_WAIT(1);
        else             CP_WAIT(0);
        __syncthreads();
        if (ti + 2 < NT) issue_tile((ti + 2) % 3, (ti + 2) * 64);

        const int st = ti % 3;
        const uint32_t kbase = sb + KS_B(st) + koff;
        const uint32_t vbase = sb + VS_B(st) + voff;
        const int*     Mk    = (const int*)(sm + MK_B(st));

        // ---- S = Q K^T ----
        float sacc[8][4];
#pragma unroll
        for (int nt = 0; nt < 8; nt++)
#pragma unroll
            for (int e = 0; e < 4; e++) sacc[nt][e] = 0.0f;

#pragma unroll
        for (int s = 0; s < 4; s++) {
            unsigned a[4];
            ldsm4(a, qa + s * 32);
#pragma unroll
            for (int np = 0; np < 4; np++) {
                unsigned kb4[4];
                ldsm4(kb4, kbase + np * 16 * HSTB + s * 32);
                mma16h(sacc[2 * np],     a, kb4[0], kb4[1]);
                mma16h(sacc[2 * np + 1], a, kb4[2], kb4[3]);
            }
        }

        // ---- mask + online softmax (exp2 domain) ----
        float mx[2] = {-1e30f, -1e30f};
#pragma unroll
        for (int nt = 0; nt < 8; nt++) {
            float mk0 = Mk[nt * 8 + t * 2]     ? 0.0f : -1e30f;
            float mk1 = Mk[nt * 8 + t * 2 + 1] ? 0.0f : -1e30f;
            sacc[nt][0] += mk0; sacc[nt][1] += mk1;
            sacc[nt][2] += mk0; sacc[nt][3] += mk1;
            mx[0] = fmaxf(mx[0], fmaxf(sacc[nt][0], sacc[nt][1]));
            mx[1] = fmaxf(mx[1], fmaxf(sacc[nt][2], sacc[nt][3]));
        }
        float corr[2];
#pragma unroll
        for (int h2 = 0; h2 < 2; h2++) {
            mx[h2] = fmaxf(mx[h2], __shfl_xor_sync(FULL, mx[h2], 1));
            mx[h2] = fmaxf(mx[h2], __shfl_xor_sync(FULL, mx[h2], 2));
            float mn = fmaxf(mrun[h2], mx[h2]);
            corr[h2] = ex2(mrun[h2] - mn);
            mrun[h2] = mn;
        }
        float ls[2] = {0.0f, 0.0f};
#pragma unroll
        for (int nt = 0; nt < 8; nt++) {
            sacc[nt][0] = ex2(sacc[nt][0] - mrun[0]);
            sacc[nt][1] = ex2(sacc[nt][1] - mrun[0]);
            sacc[nt][2] = ex2(sacc[nt][2] - mrun[1]);
            sacc[nt][3] = ex2(sacc[nt][3] - mrun[1]);
            ls[0] += sacc[nt][0] + sacc[nt][1];
            ls[1] += sacc[nt][2] + sacc[nt][3];
        }
#pragma unroll
        for (int h2 = 0; h2 < 2; h2++) {
            ls[h2] += __shfl_xor_sync(FULL, ls[h2], 1);
            ls[h2] += __shfl_xor_sync(FULL, ls[h2], 2);
            lrun[h2] = lrun[h2] * corr[h2] + ls[h2];
        }
#pragma unroll
        for (int dt = 0; dt < 8; dt++) {
            oacc[dt][0] *= corr[0]; oacc[dt][1] *= corr[0];
            oacc[dt][2] *= corr[1]; oacc[dt][3] *= corr[1];
        }

        // ---- P -> smem as fp16 (warp-private rows) ----
#pragma unroll
        for (int nt = 0; nt < 8; nt++) {
            int cb = (nt * 8 + t * 2) * 2;
            *(__half2*)(sm + PS_B + r * HSTB + cb) =
                __floats2half2_rn(sacc[nt][0], sacc[nt][1]);
            *(__half2*)(sm + PS_B + (r + 8) * HSTB + cb) =
                __floats2half2_rn(sacc[nt][2], sacc[nt][3]);
        }
        __syncwarp();

        // ---- O += P @ V ----
#pragma unroll
        for (int s = 0; s < 4; s++) {
            unsigned p4[4];
            ldsm4(p4, pa + s * 32);
#pragma unroll
            for (int dp = 0; dp < 4; dp++) {
                unsigned vb4[4];
                ldsm4t(vb4, vbase + s * 16 * HSTB + dp * 32);
                mma16h(oacc[2 * dp],     p4, vb4[0], vb4[1]);
                mma16h(oacc[2 * dp + 1], p4, vb4[2], vb4[3]);
            }
        }
        // no bottom barrier: next iteration's top barrier protects the ring
    }

    float inv[2];
    inv[0] = (mrun[0] > -9e29f) ? (1.0f / lrun[0]) : 0.0f;
    inv[1] = (mrun[1] > -9e29f) ? (1.0f / lrun[1]) : 0.0f;
#pragma unroll
    for (int h2 = 0; h2 < 2; h2++) {
        int row = q0 + r + h2 * 8;
        __half* dst = ctx + (size_t)(b * SEQ + row) * D_MODEL + hd * HDIM;
#pragma unroll
        for (int dt = 0; dt < 8; dt++) {
            *(__half2*)(dst + dt * 8 + t * 2) =
                __floats2half2_rn(oacc[dt][h2 * 2 + 0] * inv[h2],
                                  oacc[dt][h2 * 2 + 1] * inv[h2]);
        }
    }
}

// ======================= launch =======================
extern "C" void kernel_launch(void* const* d_in, const int* in_sizes, int n_in,
                              void* d_out, int out_size)
{
    const float* q   = (const float*)d_in[0];
    const float* k   = (const float*)d_in[1];
    const float* v   = (const float*)d_in[2];
    const int*   msk = (const int*)  d_in[3];
    const float* Wq  = (const float*)d_in[4];
    const float* Wk  = (const float*)d_in[5];
    const float* Wv  = (const float*)d_in[6];
    const float* Wo  = (const float*)d_in[7];
    const float* bo  = (const float*)d_in[8];
    float* out = (float*)d_out;

    __half *xq, *xk, *xv, *wq, *wk, *wv, *wo, *gq, *gk, *gv, *gc;
    cudaGetSymbolAddress((void**)&xq, g_xq);
    cudaGetSymbolAddress((void**)&xk, g_xk);
    cudaGetSymbolAddress((void**)&xv, g_xv);
    cudaGetSymbolAddress((void**)&wq, g_wq);
    cudaGetSymbolAddress((void**)&wk, g_wk);
    cudaGetSymbolAddress((void**)&wv, g_wv);
    cudaGetSymbolAddress((void**)&wo, g_wo);
    cudaGetSymbolAddress((void**)&gq, g_qh);
    cudaGetSymbolAddress((void**)&gk, g_kh);
    cudaGetSymbolAddress((void**)&gv, g_vh);
    cudaGetSymbolAddress((void**)&gc, g_ch);

    cudaFuncSetAttribute(gemm_h2,
                         cudaFuncAttributeMaxDynamicSharedMemorySize, G2_SMEM);
    cudaFuncSetAttribute(attn_h,
                         cudaFuncAttributeMaxDynamicSharedMemorySize, ATT_SMEM_BYTES);

    // pre-convert everything to fp16 (Wq scaled by 0.125 * log2(e))
    cvt_all<<<dim3(MTOK * D_MODEL / 4 / 256, 7), 256>>>(
        q, k, v, Wq, Wk, Wv, Wo, xq, xk, xv, wq, wk, wv, wo);

    dim3 gg(D_MODEL / 128, MTOK / 128);   // (8, 32)

    gemm_h2<<<gg, 256, G2_SMEM>>>(xq, wq, nullptr, gq, 1);  // Q (pre-scaled via Wq)
    gemm_h2<<<gg, 256, G2_SMEM>>>(xk, wk, nullptr, gk, 1);  // K
    gemm_h2<<<gg, 256, G2_SMEM>>>(xv, wv, nullptr, gv, 1);  // V

    dim3 ag(SEQ / 128, NHEAD, BATCH);     // (16, 16, 2)
    attn_h<<<ag, 256, ATT_SMEM_BYTES>>>(gq, gk, gv, msk, gc);

    gemm_h2<<<gg, 256, G2_SMEM>>>(gc, wo, bo, out, 0);      // O proj fp32 + bias
}

// round 17
// speedup vs baseline: 1.0522x; 1.0522x over previous
#include <cuda_runtime.h>
#include <cuda_fp16.h>
#include <cstdint>
#include <math.h>

#define D_MODEL 1024
#define NHEAD   16
#define HDIM    64
#define BATCH   2
#define SEQ     2048
#define MTOK    (BATCH * SEQ)   // 4096

// -------- scratch (static device globals; no allocation allowed) --------
__device__ __half g_xq[MTOK * D_MODEL];       // fp16 query input
__device__ __half g_xk[MTOK * D_MODEL];       // fp16 key input
__device__ __half g_xv[MTOK * D_MODEL];       // fp16 value input
__device__ __half g_wq[D_MODEL * D_MODEL];    // fp16 Wq * 0.125 * log2(e)
__device__ __half g_wk[D_MODEL * D_MODEL];    // fp16 Wk
__device__ __half g_wv[D_MODEL * D_MODEL];    // fp16 Wv
__device__ __half g_wo[D_MODEL * D_MODEL];    // fp16 Wo
__device__ __half g_qh[MTOK * D_MODEL];       // fp16 Q (pre-scaled, log2 domain)
__device__ __half g_kh[MTOK * D_MODEL];       // fp16 K
__device__ __half g_vh[MTOK * D_MODEL];       // fp16 V
__device__ __half g_ch[MTOK * D_MODEL];       // fp16 ctx

// ======================= helpers =======================
__device__ __forceinline__ uint32_t smem_u32(const void* p) {
    uint32_t a;
    asm("{ .reg .u64 t; cvta.to.shared.u64 t, %1; cvt.u32.u64 %0, t; }"
        : "=r"(a) : "l"(p));
    return a;
}

__device__ __forceinline__ float ex2(float x) {
    float y;
    asm("ex2.approx.ftz.f32 %0, %1;" : "=f"(y) : "f"(x));
    return y;
}

__device__ __forceinline__ void mma16h(float* d, const unsigned* a,
                                       unsigned b0, unsigned b1) {
    asm volatile(
        "mma.sync.aligned.m16n8k16.row.col.f32.f16.f16.f32 "
        "{%0,%1,%2,%3}, {%4,%5,%6,%7}, {%8,%9}, {%0,%1,%2,%3};"
        : "+f"(d[0]), "+f"(d[1]), "+f"(d[2]), "+f"(d[3])
        : "r"(a[0]), "r"(a[1]), "r"(a[2]), "r"(a[3]), "r"(b0), "r"(b1));
}

__device__ __forceinline__ void ldsm4(unsigned* r, uint32_t a) {
    asm volatile("ldmatrix.sync.aligned.m8n8.x4.shared.b16 {%0,%1,%2,%3}, [%4];"
                 : "=r"(r[0]), "=r"(r[1]), "=r"(r[2]), "=r"(r[3]) : "r"(a));
}
__device__ __forceinline__ void ldsm4t(unsigned* r, uint32_t a) {
    asm volatile("ldmatrix.sync.aligned.m8n8.x4.trans.shared.b16 {%0,%1,%2,%3}, [%4];"
                 : "=r"(r[0]), "=r"(r[1]), "=r"(r[2]), "=r"(r[3]) : "r"(a));
}

#define CP_A16(dst, src) \
    asm volatile("cp.async.ca.shared.global [%0], [%1], 16;" :: "r"(dst), "l"(src) : "memory")
#define CP_A4(dst, src) \
    asm volatile("cp.async.ca.shared.global [%0], [%1], 4;" :: "r"(dst), "l"(src) : "memory")
#define CP_COMMIT() asm volatile("cp.async.commit_group;" ::: "memory")
#define CP_WAIT(n)  asm volatile("cp.async.wait_group %0;" :: "n"(n) : "memory")

// ======================= pre-convert: fp32 -> fp16 =======================
#define QSCALE 0.18033688f   // 0.125 * log2(e)

__global__ __launch_bounds__(256)
void cvt_all(const float* __restrict__ q, const float* __restrict__ k,
             const float* __restrict__ v, const float* __restrict__ wq,
             const float* __restrict__ wk, const float* __restrict__ wv,
             const float* __restrict__ wo,
             __half* __restrict__ xq, __half* __restrict__ xk,
             __half* __restrict__ xv, __half* __restrict__ hwq,
             __half* __restrict__ hwk, __half* __restrict__ hwv,
             __half* __restrict__ hwo)
{
    const float* src; __half* dst; int n; float sc = 1.0f;
    switch (blockIdx.y) {
        case 0: src = q;  dst = xq;  n = MTOK * D_MODEL; break;
        case 1: src = k;  dst = xk;  n = MTOK * D_MODEL; break;
        case 2: src = v;  dst = xv;  n = MTOK * D_MODEL; break;
        case 3: src = wq; dst = hwq; n = D_MODEL * D_MODEL; sc = QSCALE; break;
        case 4: src = wk; dst = hwk; n = D_MODEL * D_MODEL; break;
        case 5: src = wv; dst = hwv; n = D_MODEL * D_MODEL; break;
        default: src = wo; dst = hwo; n = D_MODEL * D_MODEL; break;
    }
    int i = (blockIdx.x * 256 + threadIdx.x) * 4;
    if (i < n) {
        float4 f = *(const float4*)(src + i);
        *(__half2*)(dst + i)     = __floats2half2_rn(f.x * sc, f.y * sc);
        *(__half2*)(dst + i + 2) = __floats2half2_rn(f.z * sc, f.w * sc);
    }
}

// ======================= GEMM core (pure fp16, cp.async 3-stage, BK=64) =======================
#define G2ST   144                 // row stride bytes (72 halves; conflict-free LDSM)
#define G2_OP  (128 * G2ST)        // 18432 per operand per stage
#define G2_STAGE (2 * G2_OP)       // 36864
#define G2_SMEM  (3 * G2_STAGE)    // 110592

template <int OUTMODE>
__device__ __forceinline__ void gemm_body(
    const __half* __restrict__ X, const __half* __restrict__ W,
    const float* __restrict__ bias, void* __restrict__ Yv,
    char* smem, int bm, int bn)
{
    const uint32_t sb = smem_u32(smem);

    const int tid  = threadIdx.x;
    const int lane = tid & 31;
    const int wid  = tid >> 5;
    const int wm   = (wid & 3) * 32;
    const int wn   = (wid >> 2) * 64;
    const int g    = lane >> 2;
    const int t    = lane & 3;
    const int K    = D_MODEL;

    const int l7  = lane & 7;
    const int lb3 = (lane >> 3) & 1;
    const int lb4 = lane >> 4;

    int lrow[4], lc[4];
#pragma unroll
    for (int i = 0; i < 4; i++) {
        int idx = tid + i * 256;
        lrow[i] = idx >> 3;
        lc[i]   = idx & 7;
    }

    auto issue = [&](int s) {
        uint32_t st = sb + (uint32_t)(s % 3) * G2_STAGE;
        int k0 = s * 64;
#pragma unroll
        for (int i = 0; i < 4; i++) {
            uint32_t doff = (uint32_t)(lrow[i] * G2ST + lc[i] * 16);
            CP_A16(st + doff,         X + (size_t)(bm + lrow[i]) * K + k0 + lc[i] * 8);
            CP_A16(st + G2_OP + doff, W + (size_t)(bn + lrow[i]) * K + k0 + lc[i] * 8);
        }
        CP_COMMIT();
    };

    uint32_t aoffb[2];
#pragma unroll
    for (int mt = 0; mt < 2; mt++)
        aoffb[mt] = (uint32_t)((wm + mt * 16 + l7 + (lane & 8)) * G2ST) + lb4 * 16;
    const uint32_t boffb = (uint32_t)((wn + l7 + lb4 * 8) * G2ST) + lb3 * 16;

    float acc[2][8][4];
#pragma unroll
    for (int mt = 0; mt < 2; mt++)
#pragma unroll
        for (int nt = 0; nt < 8; nt++)
#pragma unroll
            for (int e = 0; e < 4; e++) acc[mt][nt][e] = 0.0f;

    const int NS = K / 64;   // 16
    issue(0); issue(1);

    for (int s = 0; s < NS; s++) {
        if (s + 1 < NS) CP_WAIT(1);
        else            CP_WAIT(0);
        __syncthreads();
        if (s + 2 < NS) issue(s + 2);

        uint32_t ab = sb + (uint32_t)(s % 3) * G2_STAGE;
        uint32_t bb = ab + G2_OP;
#pragma unroll
        for (int s16 = 0; s16 < 4; s16++) {
            // batch ALL fragment loads first (6 LDSM in flight), then 16 MMAs
            unsigned a[2][4], b4[4][4];
            ldsm4(a[0], ab + aoffb[0] + s16 * 32);
            ldsm4(a[1], ab + aoffb[1] + s16 * 32);
#pragma unroll
            for (int np = 0; np < 4; np++)
                ldsm4(b4[np], bb + boffb + np * 16 * G2ST + s16 * 32);
#pragma unroll
            for (int np = 0; np < 4; np++) {
                mma16h(acc[0][2 * np],     a[0], b4[np][0], b4[np][1]);
                mma16h(acc[0][2 * np + 1], a[0], b4[np][2], b4[np][3]);
                mma16h(acc[1][2 * np],     a[1], b4[np][0], b4[np][1]);
                mma16h(acc[1][2 * np + 1], a[1], b4[np][2], b4[np][3]);
            }
        }
    }

#pragma unroll
    for (int mt = 0; mt < 2; mt++)
#pragma unroll
        for (int hh = 0; hh < 2; hh++) {
            int row = bm + wm + mt * 16 + g + hh * 8;
#pragma unroll
            for (int nt = 0; nt < 8; nt++) {
                int col = bn + wn + nt * 8 + t * 2;
                float x = acc[mt][nt][hh * 2 + 0];
                float y = acc[mt][nt][hh * 2 + 1];
                if (OUTMODE) {
                    *(__half2*)((__half*)Yv + (size_t)row * D_MODEL + col) =
                        __floats2half2_rn(x, y);
                } else {
                    float2 v;
                    v.x = x + bias[col];
                    v.y = y + bias[col + 1];
                    *(float2*)((float*)Yv + (size_t)row * D_MODEL + col) = v;
                }
            }
        }
}

// fused Q/K/V projections: blockIdx.z selects the (X, W, Y) triple
__global__ __launch_bounds__(256, 2)
void gemm_qkv(const __half* __restrict__ xq, const __half* __restrict__ xk,
              const __half* __restrict__ xv,
              const __half* __restrict__ wq, const __half* __restrict__ wk,
              const __half* __restrict__ wv,
              __half* __restrict__ yq, __half* __restrict__ yk,
              __half* __restrict__ yv)
{
    extern __shared__ char smem[];
    const __half* X; const __half* W; __half* Y;
    if (blockIdx.z == 0)      { X = xq; W = wq; Y = yq; }
    else if (blockIdx.z == 1) { X = xk; W = wk; Y = yk; }
    else                      { X = xv; W = wv; Y = yv; }
    gemm_body<1>(X, W, nullptr, Y, smem, blockIdx.y * 128, blockIdx.x * 128);
}

// output projection: fp16 in, fp32 + bias out
__global__ __launch_bounds__(256, 2)
void gemm_out(const __half* __restrict__ X, const __half* __restrict__ W,
              const float* __restrict__ bias, float* __restrict__ Y)
{
    extern __shared__ char smem[];
    gemm_body<0>(X, W, bias, Y, smem, blockIdx.y * 128, blockIdx.x * 128);
}

// ======================= Flash attention (3-stage ring, exp2 domain) =======================
#define HSTB 144                       // row stride bytes (72 halves)
#define QS_B   0                       // 128 rows
#define KS_B(s) (18432 + (s) * 9216)   // 64 rows, 3 stages
#define VS_B(s) (46080 + (s) * 9216)   // 64 rows, 3 stages
#define PS_B   73728                   // 128 rows
#define MK_B(s) (92160 + (s) * 256)    // 64 ints, 3 stages
#define ATT_SMEM_BYTES (92928)

__global__ __launch_bounds__(256, 2)
void attn_h(const __half* __restrict__ Qb, const __half* __restrict__ Kb,
            const __half* __restrict__ Vb, const int* __restrict__ mask,
            __half* __restrict__ ctx)
{
    extern __shared__ char sm[];
    const uint32_t sb = smem_u32(sm);

    const int tid  = threadIdx.x;
    const int lane = tid & 31;
    const int wid  = tid >> 5;
    const int g    = lane >> 2;
    const int t    = lane & 3;
    const int q0   = blockIdx.x * 128;
    const int hd   = blockIdx.y;
    const int b    = blockIdx.z;

    const __half* Qg = Qb + (size_t)(b * SEQ) * D_MODEL + hd * HDIM;
    const __half* Kg = Kb + (size_t)(b * SEQ) * D_MODEL + hd * HDIM;
    const __half* Vg = Vb + (size_t)(b * SEQ) * D_MODEL + hd * HDIM;
    const int*    Mg = mask + b * SEQ;

    int jr[2], jc[2];
#pragma unroll
    for (int i = 0; i < 2; i++) {
        int idx = tid + i * 256;
        jr[i] = idx >> 3;
        jc[i] = idx & 7;
    }

    auto issue_tile = [&](int st, int kb) {
#pragma unroll
        for (int i = 0; i < 2; i++) {
            uint32_t doff = (uint32_t)(jr[i] * HSTB + jc[i] * 16);
            CP_A16(sb + KS_B(st) + doff, Kg + (size_t)(kb + jr[i]) * D_MODEL + jc[i] * 8);
            CP_A16(sb + VS_B(st) + doff, Vg + (size_t)(kb + jr[i]) * D_MODEL + jc[i] * 8);
        }
        if (tid < 64) CP_A4(sb + MK_B(st) + tid * 4, Mg + kb + tid);
        CP_COMMIT();
    };

    issue_tile(0, 0);
    issue_tile(1, 64);

#pragma unroll
    for (int i = 0; i < 4; i++) {
        int idx = tid + i * 256;
        int row = idx >> 3;
        int c8  = idx & 7;
        *(uint4*)(sm + QS_B + row * HSTB + c8 * 16) =
            *(const uint4*)(Qg + (size_t)(q0 + row) * D_MODEL + c8 * 8);
    }

    const int l7  = lane & 7;
    const int lb3 = (lane >> 3) & 1;
    const int lb4 = lane >> 4;
    const uint32_t qa = sb + QS_B + (uint32_t)((wid * 16 + l7 + (lane & 8)) * HSTB) + lb4 * 16;
    const uint32_t pa = sb + PS_B + (uint32_t)((wid * 16 + l7 + (lane & 8)) * HSTB) + lb4 * 16;
    const uint32_t koff = (uint32_t)((l7 + lb4 * 8) * HSTB) + lb3 * 16;
    const uint32_t voff = (uint32_t)((l7 + lb3 * 8) * HSTB) + lb4 * 16;

    float oacc[8][4];
#pragma unroll
    for (int dt = 0; dt < 8; dt++)
#pragma unroll
        for (int e = 0; e < 4; e++) oacc[dt][e] = 0.0f;
    float mrun[2] = {-1e30f, -1e30f};
    float lrun[2] = {0.0f, 0.0f};

    const int r = wid * 16 + g;
    const unsigned FULL = 0xffffffffu;
    const int NT = SEQ / 64;   // 32

    for (int ti = 0; ti < NT; ti++) {
        if (ti + 1 < NT) CP_WAIT(1);
        else             CP_WAIT(0);
        __syncthreads();
        if (ti + 2 < NT) issue_tile((ti + 2) % 3, (ti + 2) * 64);

        const int st = ti % 3;
        const uint32_t kbase = sb + KS_B(st) + koff;
        const uint32_t vbase = sb + VS_B(st) + voff;
        const int*     Mk    = (const int*)(sm + MK_B(st));

        float sacc[8][4];
#pragma unroll
        for (int nt = 0; nt < 8; nt++)
#pragma unroll
            for (int e = 0; e < 4; e++) sacc[nt][e] = 0.0f;

#pragma unroll
        for (int s = 0; s < 4; s++) {
            unsigned a[4], kb4[4][4];
            ldsm4(a, qa + s * 32);
#pragma unroll
            for (int np = 0; np < 4; np++)
                ldsm4(kb4[np], kbase + np * 16 * HSTB + s * 32);
#pragma unroll
            for (int np = 0; np < 4; np++) {
                mma16h(sacc[2 * np],     a, kb4[np][0], kb4[np][1]);
                mma16h(sacc[2 * np + 1], a, kb4[np][2], kb4[np][3]);
            }
        }

        float mx[2] = {-1e30f, -1e30f};
#pragma unroll
        for (int nt = 0; nt < 8; nt++) {
            float mk0 = Mk[nt * 8 + t * 2]     ? 0.0f : -1e30f;
            float mk1 = Mk[nt * 8 + t * 2 + 1] ? 0.0f : -1e30f;
            sacc[nt][0] += mk0; sacc[nt][1] += mk1;
            sacc[nt][2] += mk0; sacc[nt][3] += mk1;
            mx[0] = fmaxf(mx[0], fmaxf(sacc[nt][0], sacc[nt][1]));
            mx[1] = fmaxf(mx[1], fmaxf(sacc[nt][2], sacc[nt][3]));
        }
        float corr[2];
#pragma unroll
        for (int h2 = 0; h2 < 2; h2++) {
            mx[h2] = fmaxf(mx[h2], __shfl_xor_sync(FULL, mx[h2], 1));
            mx[h2] = fmaxf(mx[h2], __shfl_xor_sync(FULL, mx[h2], 2));
            float mn = fmaxf(mrun[h2], mx[h2]);
            corr[h2] = ex2(mrun[h2] - mn);
            mrun[h2] = mn;
        }
        float ls[2] = {0.0f, 0.0f};
#pragma unroll
        for (int nt = 0; nt < 8; nt++) {
            sacc[nt][0] = ex2(sacc[nt][0] - mrun[0]);
            sacc[nt][1] = ex2(sacc[nt][1] - mrun[0]);
            sacc[nt][2] = ex2(sacc[nt][2] - mrun[1]);
            sacc[nt][3] = ex2(sacc[nt][3] - mrun[1]);
            ls[0] += sacc[nt][0] + sacc[nt][1];
            ls[1] += sacc[nt][2] + sacc[nt][3];
        }
#pragma unroll
        for (int h2 = 0; h2 < 2; h2++) {
            ls[h2] += __shfl_xor_sync(FULL, ls[h2], 1);
            ls[h2] += __shfl_xor_sync(FULL, ls[h2], 2);
            lrun[h2] = lrun[h2] * corr[h2] + ls[h2];
        }
#pragma unroll
        for (int dt = 0; dt < 8; dt++) {
            oacc[dt][0] *= corr[0]; oacc[dt][1] *= corr[0];
            oacc[dt][2] *= corr[1]; oacc[dt][3] *= corr[1];
        }

#pragma unroll
        for (int nt = 0; nt < 8; nt++) {
            int cb = (nt * 8 + t * 2) * 2;
            *(__half2*)(sm + PS_B + r * HSTB + cb) =
                __floats2half2_rn(sacc[nt][0], sacc[nt][1]);
            *(__half2*)(sm + PS_B + (r + 8) * HSTB + cb) =
                __floats2half2_rn(sacc[nt][2], sacc[nt][3]);
        }
        __syncwarp();

#pragma unroll
        for (int s = 0; s < 4; s++) {
            unsigned p4[4], vb4[4][4];
            ldsm4(p4, pa + s * 32);
#pragma unroll
            for (int dp = 0; dp < 4; dp++)
                ldsm4t(vb4[dp], vbase + s * 16 * HSTB + dp * 32);
#pragma unroll
            for (int dp = 0; dp < 4; dp++) {
                mma16h(oacc[2 * dp],     p4, vb4[dp][0], vb4[dp][1]);
                mma16h(oacc[2 * dp + 1], p4, vb4[dp][2], vb4[dp][3]);
            }
        }
    }

    float inv[2];
    inv[0] = (mrun[0] > -9e29f) ? (1.0f / lrun[0]) : 0.0f;
    inv[1] = (mrun[1] > -9e29f) ? (1.0f / lrun[1]) : 0.0f;
#pragma unroll
    for (int h2 = 0; h2 < 2; h2++) {
        int row = q0 + r + h2 * 8;
        __half* dst = ctx + (size_t)(b * SEQ + row) * D_MODEL + hd * HDIM;
#pragma unroll
        for (int dt = 0; dt < 8; dt++) {
            *(__half2*)(dst + dt * 8 + t * 2) =
                __floats2half2_rn(oacc[dt][h2 * 2 + 0] * inv[h2],
                                  oacc[dt][h2 * 2 + 1] * inv[h2]);
        }
    }
}

// ======================= launch =======================
extern "C" void kernel_launch(void* const* d_in, const int* in_sizes, int n_in,
                              void* d_out, int out_size)
{
    const float* q   = (const float*)d_in[0];
    const float* k   = (const float*)d_in[1];
    const float* v   = (const float*)d_in[2];
    const int*   msk = (const int*)  d_in[3];
    const float* Wq  = (const float*)d_in[4];
    const float* Wk  = (const float*)d_in[5];
    const float* Wv  = (const float*)d_in[6];
    const float* Wo  = (const float*)d_in[7];
    const float* bo  = (const float*)d_in[8];
    float* out = (float*)d_out;

    __half *xq, *xk, *xv, *wq, *wk, *wv, *wo, *gq, *gk, *gv, *gc;
    cudaGetSymbolAddress((void**)&xq, g_xq);
    cudaGetSymbolAddress((void**)&xk, g_xk);
    cudaGetSymbolAddress((void**)&xv, g_xv);
    cudaGetSymbolAddress((void**)&wq, g_wq);
    cudaGetSymbolAddress((void**)&wk, g_wk);
    cudaGetSymbolAddress((void**)&wv, g_wv);
    cudaGetSymbolAddress((void**)&wo, g_wo);
    cudaGetSymbolAddress((void**)&gq, g_qh);
    cudaGetSymbolAddress((void**)&gk, g_kh);
    cudaGetSymbolAddress((void**)&gv, g_vh);
    cudaGetSymbolAddress((void**)&gc, g_ch);

    cudaFuncSetAttribute(gemm_qkv,
                         cudaFuncAttributeMaxDynamicSharedMemorySize, G2_SMEM);
    cudaFuncSetAttribute(gemm_out,
                         cudaFuncAttributeMaxDynamicSharedMemorySize, G2_SMEM);
    cudaFuncSetAttribute(attn_h,
                         cudaFuncAttributeMaxDynamicSharedMemorySize, ATT_SMEM_BYTES);

    // pre-convert everything to fp16 (Wq scaled by 0.125 * log2(e))
    cvt_all<<<dim3(MTOK * D_MODEL / 4 / 256, 7), 256>>>(
        q, k, v, Wq, Wk, Wv, Wo, xq, xk, xv, wq, wk, wv, wo);

    // fused Q/K/V projections: one launch, 768 CTAs
    gemm_qkv<<<dim3(D_MODEL / 128, MTOK / 128, 3), 256, G2_SMEM>>>(
        xq, xk, xv, wq, wk, wv, gq, gk, gv);

    dim3 ag(SEQ / 128, NHEAD, BATCH);     // (16, 16, 2)
    attn_h<<<ag, 256, ATT_SMEM_BYTES>>>(gq, gk, gv, msk, gc);

    gemm_out<<<dim3(D_MODEL / 128, MTOK / 128), 256, G2_SMEM>>>(gc, wo, bo, out);
}